// round 1
// baseline (speedup 1.0000x reference)
#include <cuda_runtime.h>
#include <cstdint>

// Problem constants
#define NPTS   32768            // 32 * 32 * 32 points
#define DIM    64               // embedding dim
#define NE     1024             // codebook size
#define HW     1024             // 32*32 spatial
#define BHW    65536            // 64 channels * 1024 hw (per-batch stride in z)

// Output layout (flat concat of reference return tuple, float32):
// loss[1], z_q[2097152], perplexity[1], min_encodings[33554432], indices[32768]
#define OFF_LOSS 0ULL
#define OFF_ZQ   1ULL
#define OFF_PERP 2097153ULL
#define OFF_ENC  2097154ULL
#define OFF_IDX  35651586ULL

__device__ float        d_esq[NE];
__device__ unsigned int d_count[NE];
__device__ float        d_loss;

// ---------------------------------------------------------------- helpers
struct __align__(16) ull2 { unsigned long long a, b; };

static __device__ __forceinline__ unsigned long long pk2(float v) {
    unsigned long long r;
    asm("mov.b64 %0, {%1,%2};" : "=l"(r) : "f"(v), "f"(v));
    return r;
}
static __device__ __forceinline__ void ffma2(unsigned long long& d,
                                             unsigned long long a,
                                             unsigned long long b) {
    // packed 2-wide fp32 FMA (Blackwell f32x2 pipe) — 2x scalar FFMA rate
    asm("fma.rn.f32x2 %0, %1, %2, %0;" : "+l"(d) : "l"(a), "l"(b));
}
static __device__ __forceinline__ float2 upk(unsigned long long v) {
    float2 f;
    asm("mov.b64 {%0,%1}, %2;" : "=f"(f.x), "=f"(f.y) : "l"(v));
    return f;
}
// monotonic float->uint mapping for ordered compare
static __device__ __forceinline__ unsigned int ordf(float x) {
    unsigned int b = __float_as_uint(x);
    return b ^ (unsigned int)(((int)b >> 31) | 0x80000000);
}

// ---------------------------------------------------------------- prep
__global__ void prep_kernel(const float* __restrict__ emb) {
    int c = blockIdx.x * blockDim.x + threadIdx.x;
    if (c < NE) {
        const float* r = emb + c * DIM;
        float s = 0.f;
        #pragma unroll
        for (int k = 0; k < DIM; ++k) s = __fadd_rn(s, __fmul_rn(r[k], r[k]));
        d_esq[c]   = s;
        d_count[c] = 0u;
    }
    if (c == 0) d_loss = 0.f;
}

// ---------------------------------------------------------------- zero-fill one-hot region (8B aligned)
__global__ void zero_kernel(unsigned long long* __restrict__ p, long long n8) {
    long long i      = (long long)blockIdx.x * blockDim.x + threadIdx.x;
    long long stride = (long long)gridDim.x * blockDim.x;
    for (; i < n8; i += stride) p[i] = 0ULL;
}

// ---------------------------------------------------------------- main fused kernel
// block: 128 threads = 16 code-threads x 8 point-threads
// block tile: 64 points x 128 codes per chunk (8 chunks cover 1024 codes)
// thread tile: 8 codes x 8 points, points packed as f32x2 pairs
__global__ void __launch_bounds__(128, 4)
vq_main_kernel(const float* __restrict__ z, const float* __restrict__ emb,
               float* __restrict__ out)
{
    __shared__ __align__(16) float zs[DIM][64];     // [k][pt]   16 KB
    __shared__ __align__(16) float es[128][DIM];    // [c][k]    32 KB
    __shared__ float zsq_s[64];
    __shared__ unsigned long long red[16][64];      //           8 KB

    const int tid  = threadIdx.x;
    const int pt_t = tid & 7;     // 0..7  (point group)
    const int ct   = tid >> 3;    // 0..15 (code group)
    const int pt0  = blockIdx.x * 64;
    const int b    = pt0 >> 10;
    const int hw0  = pt0 & 1023;
    const float* zb = z + (size_t)b * BHW + hw0;

    // load z tile [k][pt], coalesced over hw
    for (int i = tid; i < 4096; i += 128) {
        int k = i >> 6, p = i & 63;
        zs[k][p] = zb[(size_t)k * HW + p];
    }
    __syncthreads();

    // per-point ||z||^2 in sequential fp32 rn (match reference rounding structure)
    if (tid < 64) {
        float s = 0.f;
        #pragma unroll
        for (int k = 0; k < DIM; ++k) {
            float v = zs[k][tid];
            s = __fadd_rn(s, __fmul_rn(v, v));
        }
        zsq_s[tid] = s;
    }
    __syncthreads();

    float zqr[8];
    #pragma unroll
    for (int l = 0; l < 8; ++l) zqr[l] = zsq_s[pt_t * 8 + l];

    unsigned long long best[8];
    #pragma unroll
    for (int j = 0; j < 8; ++j) best[j] = 0xFFFFFFFFFFFFFFFFULL;

    for (int chunk = 0; chunk < 8; ++chunk) {
        __syncthreads();   // previous chunk's es consumers done
        {   // load 128 codes x 64 dims, direct coalesced copy (row-major match)
            const float4* esrc = (const float4*)(emb + (size_t)chunk * 128 * DIM);
            float4*       edst = (float4*)&es[0][0];
            #pragma unroll
            for (int i = 0; i < 16; ++i) edst[tid + 128 * i] = esrc[tid + 128 * i];
        }
        __syncthreads();

        unsigned long long acc[8][4];
        #pragma unroll
        for (int j = 0; j < 8; ++j)
            #pragma unroll
            for (int p = 0; p < 4; ++p) acc[j][p] = 0ULL;

        #pragma unroll 4
        for (int k4 = 0; k4 < DIM; k4 += 4) {
            #pragma unroll
            for (int kk = 0; kk < 4; ++kk) {
                const int k = k4 + kk;
                ull2 za = *(const ull2*)&zs[k][pt_t * 8];
                ull2 zc = *(const ull2*)&zs[k][pt_t * 8 + 4];
                unsigned long long zp0 = za.a, zp1 = za.b, zp2 = zc.a, zp3 = zc.b;
                #pragma unroll
                for (int j = 0; j < 8; ++j) {
                    unsigned long long e2 = pk2(es[ct * 8 + j][k]);
                    ffma2(acc[j][0], zp0, e2);
                    ffma2(acc[j][1], zp1, e2);
                    ffma2(acc[j][2], zp2, e2);
                    ffma2(acc[j][3], zp3, e2);
                }
            }
        }

        // distances + running argmin (u64 key -> first-index tie-break like jnp.argmin)
        #pragma unroll
        for (int j = 0; j < 8; ++j) {
            int   code = chunk * 128 + ct * 8 + j;
            float esq  = d_esq[code];
            #pragma unroll
            for (int p = 0; p < 4; ++p) {
                float2 dot = upk(acc[j][p]);
                {
                    float t = __fadd_rn(zqr[p * 2], esq);
                    float d = __fadd_rn(t, -2.0f * dot.x);
                    unsigned long long k64 =
                        ((unsigned long long)ordf(d) << 32) | (unsigned)code;
                    if (k64 < best[p * 2]) best[p * 2] = k64;
                }
                {
                    float t = __fadd_rn(zqr[p * 2 + 1], esq);
                    float d = __fadd_rn(t, -2.0f * dot.y);
                    unsigned long long k64 =
                        ((unsigned long long)ordf(d) << 32) | (unsigned)code;
                    if (k64 < best[p * 2 + 1]) best[p * 2 + 1] = k64;
                }
            }
        }
    }

    // cross-thread argmin reduction per point
    __syncthreads();
    #pragma unroll
    for (int j = 0; j < 8; ++j) red[ct][pt_t * 8 + j] = best[j];
    __syncthreads();

    float errsum = 0.f;
    if (tid < 64) {
        unsigned long long bk = red[0][tid];
        #pragma unroll
        for (int t = 1; t < 16; ++t) {
            unsigned long long v = red[t][tid];
            if (v < bk) bk = v;
        }
        int idx = (int)(unsigned int)bk;
        int n   = pt0 + tid;

        out[OFF_IDX + n] = (float)idx;
        atomicAdd(&d_count[idx], 1u);
        out[OFF_ENC + (unsigned long long)n * NE + (unsigned)idx] = 1.0f;

        // z_q gather + loss partial (straight-through: z_q_out == z_q in value)
        const float* er = emb + (size_t)idx * DIM;
        float* zq = out + OFF_ZQ + (size_t)b * BHW + hw0 + tid;
        #pragma unroll
        for (int c = 0; c < DIM; ++c) {
            float e  = __ldg(er + c);
            float zv = zs[c][tid];
            float df = e - zv;
            errsum   = fmaf(df, df, errsum);
            zq[(size_t)c * HW] = e;
        }
    }
    // reduce errsum over the 64 active threads (warps 0,1)
    #pragma unroll
    for (int o = 16; o > 0; o >>= 1)
        errsum += __shfl_down_sync(0xFFFFFFFFu, errsum, o);
    if (tid < 64 && (tid & 31) == 0) atomicAdd(&d_loss, errsum);
}

// ---------------------------------------------------------------- finalize scalars
__global__ void finalize_kernel(float* __restrict__ out) {
    __shared__ float warp_s[32];
    int t = threadIdx.x;  // 1024 threads
    float em   = (float)d_count[t] * (1.0f / 32768.0f);
    float v    = em * logf(em + 1e-10f);
    #pragma unroll
    for (int o = 16; o > 0; o >>= 1) v += __shfl_down_sync(0xFFFFFFFFu, v, o);
    if ((t & 31) == 0) warp_s[t >> 5] = v;
    __syncthreads();
    if (t < 32) {
        float w = warp_s[t];
        #pragma unroll
        for (int o = 16; o > 0; o >>= 1) w += __shfl_down_sync(0xFFFFFFFFu, w, o);
        if (t == 0) {
            out[OFF_PERP] = expf(-w);
            out[OFF_LOSS] = 1.25f * d_loss * (1.0f / 2097152.0f);
        }
    }
}

// ---------------------------------------------------------------- launch
extern "C" void kernel_launch(void* const* d_in, const int* in_sizes, int n_in,
                              void* d_out, int out_size) {
    const float* z   = (const float*)d_in[0];
    const float* emb = (const float*)d_in[1];
    float*       out = (float*)d_out;

    prep_kernel<<<4, 256>>>(emb);
    // zero the 33,554,432-float one-hot region (8B-aligned at OFF_ENC)
    zero_kernel<<<4096, 256>>>((unsigned long long*)(out + OFF_ENC),
                               (long long)(33554432 / 2));
    vq_main_kernel<<<NPTS / 64, 128>>>(z, emb, out);
    finalize_kernel<<<1, 1024>>>(out);
}

// round 2
// speedup vs baseline: 1.3335x; 1.3335x over previous
#include <cuda_runtime.h>
#include <cstdint>

// Problem constants
#define NPTS   32768            // 32 * 32 * 32 points
#define DIM    64               // embedding dim
#define NE     1024             // codebook size
#define HW     1024             // 32*32 spatial
#define BHW    65536            // 64 channels * 1024 hw (per-batch stride in z)
#define PTSB   32               // points per block

// Output layout (flat concat of reference return tuple, float32):
// loss[1], z_q[2097152], perplexity[1], min_encodings[33554432], indices[32768]
#define OFF_LOSS 0ULL
#define OFF_ZQ   1ULL
#define OFF_PERP 2097153ULL
#define OFF_ENC  2097154ULL
#define OFF_IDX  35651586ULL

__device__ float        d_esq[NE];
__device__ float        d_est[DIM * NE];   // transposed codebook [k][c]
__device__ unsigned int d_count[NE];
__device__ float        d_loss;

// ---------------------------------------------------------------- helpers
static __device__ __forceinline__ unsigned long long pk2(float v) {
    unsigned long long r;
    asm("mov.b64 %0, {%1,%2};" : "=l"(r) : "f"(v), "f"(v));
    return r;
}
static __device__ __forceinline__ void ffma2(unsigned long long& d,
                                             unsigned long long a,
                                             unsigned long long b) {
    // packed 2-wide fp32 FMA (Blackwell f32x2 pipe)
    asm("fma.rn.f32x2 %0, %1, %2, %0;" : "+l"(d) : "l"(a), "l"(b));
}
static __device__ __forceinline__ float2 upk(unsigned long long v) {
    float2 f;
    asm("mov.b64 {%0,%1}, %2;" : "=f"(f.x), "=f"(f.y) : "l"(v));
    return f;
}
// monotonic float->uint mapping for ordered compare
static __device__ __forceinline__ unsigned int ordf(float x) {
    unsigned int b = __float_as_uint(x);
    return b ^ (unsigned int)(((int)b >> 31) | 0x80000000);
}

// ---------------------------------------------------------------- prep
// per-code ||e||^2, transposed codebook, reset counters
__global__ void prep_kernel(const float* __restrict__ emb) {
    int c = blockIdx.x * blockDim.x + threadIdx.x;   // 0..1023
    if (c < NE) {
        const float* r = emb + c * DIM;
        float s = 0.f;
        #pragma unroll
        for (int k = 0; k < DIM; ++k) {
            float v = r[k];
            s = __fadd_rn(s, __fmul_rn(v, v));
            d_est[k * NE + c] = v;                   // coalesced per k across lanes
        }
        d_esq[c]   = s;
        d_count[c] = 0u;
    }
    if (c == 0) d_loss = 0.f;
}

// ---------------------------------------------------------------- main fused kernel
// block: 128 threads = 16 code-threads (ct) x 8 point-threads (pt_t)
// block tile: 32 points x 128 codes per chunk (8 chunks -> 1024 codes)
// thread tile: 4 points x 8 codes; f32x2 lanes = code pairs
__global__ void __launch_bounds__(128, 4)
vq_main_kernel(const float* __restrict__ z, const float* __restrict__ emb,
               float* __restrict__ out)
{
    __shared__ __align__(16) float zs[DIM][PTSB];    // [k][pt]  8 KB, conflict-free rows
    __shared__ __align__(16) float es[DIM][128];     // [k][c]   32 KB (transposed chunk)
    __shared__ float zsq_s[PTSB];
    __shared__ unsigned long long red[16][PTSB];     // 4 KB

    const int tid  = threadIdx.x;
    const int pt_t = tid & 7;     // 0..7  (point group of 4)
    const int ct   = tid >> 3;    // 0..15 (code group of 8)
    const int pt0  = blockIdx.x * PTSB;
    const int b    = pt0 >> 10;
    const int hw0  = pt0 & 1023;
    const float* zb = z + (size_t)b * BHW + hw0;

    // load z tile [k][pt] (coalesced: one row per warp-iteration)
    #pragma unroll
    for (int i = 0; i < 16; ++i) {
        int f = i * 128 + tid;
        int k = f >> 5, p = f & 31;
        zs[k][p] = zb[(size_t)k * HW + p];
    }

    // fused zero-fill of this block's one-hot rows (base is 8-mod-16 aligned)
    {
        float* encb = out + OFF_ENC + (size_t)pt0 * NE;   // 32768 floats
        if (tid == 0) {
            encb[0] = 0.f; encb[1] = 0.f;
            encb[32766] = 0.f; encb[32767] = 0.f;
        }
        float4* e4 = (float4*)(encb + 2);                 // 16B aligned
        #pragma unroll
        for (int i = 0; i < 64; ++i) {
            int j = tid + 128 * i;
            if (j < 8191) e4[j] = make_float4(0.f, 0.f, 0.f, 0.f);
        }
    }
    __syncthreads();

    // per-point ||z||^2, sequential fp32 rn (matches reference rounding)
    if (tid < PTSB) {
        float s = 0.f;
        #pragma unroll
        for (int k = 0; k < DIM; ++k) {
            float v = zs[k][tid];
            s = __fadd_rn(s, __fmul_rn(v, v));
        }
        zsq_s[tid] = s;
    }

    unsigned long long best[4];
    #pragma unroll
    for (int p = 0; p < 4; ++p) best[p] = 0xFFFFFFFFFFFFFFFFULL;

    for (int chunk = 0; chunk < 8; ++chunk) {
        __syncthreads();   // previous chunk's es consumers done (also covers zsq_s)
        // load transposed es chunk [64][128] from d_est, coalesced float4
        #pragma unroll
        for (int i = 0; i < 16; ++i) {
            int f  = i * 128 + tid;        // 0..2047 float4s
            int k  = f >> 5;               // 32 float4 per row
            int c4 = f & 31;
            *(float4*)&es[k][c4 * 4] =
                *(const float4*)&d_est[(size_t)k * NE + chunk * 128 + c4 * 4];
        }
        __syncthreads();

        unsigned long long acc[4][4];      // [point][code-pair]
        #pragma unroll
        for (int p = 0; p < 4; ++p)
            #pragma unroll
            for (int j = 0; j < 4; ++j) acc[p][j] = 0ULL;

        #pragma unroll 8
        for (int k = 0; k < DIM; ++k) {
            float4 zv = *(const float4*)&zs[k][pt_t * 4];
            unsigned long long z0 = pk2(zv.x), z1 = pk2(zv.y);
            unsigned long long z2 = pk2(zv.z), z3 = pk2(zv.w);
            const unsigned long long* ep =
                (const unsigned long long*)&es[k][ct * 8];
            #pragma unroll
            for (int j = 0; j < 4; ++j) {
                unsigned long long e2 = ep[j];     // codes (2j, 2j+1) of group
                ffma2(acc[0][j], z0, e2);
                ffma2(acc[1][j], z1, e2);
                ffma2(acc[2][j], z2, e2);
                ffma2(acc[3][j], z3, e2);
            }
        }

        // distances + running argmin (u64 key -> first-index tie-break)
        const int cbase = chunk * 128 + ct * 8;
        #pragma unroll
        for (int j = 0; j < 4; ++j) {
            float esq0 = __ldg(&d_esq[cbase + 2 * j]);
            float esq1 = __ldg(&d_esq[cbase + 2 * j + 1]);
            #pragma unroll
            for (int p = 0; p < 4; ++p) {
                float zq2 = zsq_s[pt_t * 4 + p];
                float2 dot = upk(acc[p][j]);
                {
                    float d = __fadd_rn(__fadd_rn(zq2, esq0), -2.0f * dot.x);
                    unsigned long long k64 =
                        ((unsigned long long)ordf(d) << 32) | (unsigned)(cbase + 2 * j);
                    if (k64 < best[p]) best[p] = k64;
                }
                {
                    float d = __fadd_rn(__fadd_rn(zq2, esq1), -2.0f * dot.y);
                    unsigned long long k64 =
                        ((unsigned long long)ordf(d) << 32) | (unsigned)(cbase + 2 * j + 1);
                    if (k64 < best[p]) best[p] = k64;
                }
            }
        }
    }

    // cross-thread argmin reduction per point
    __syncthreads();
    #pragma unroll
    for (int p = 0; p < 4; ++p) red[ct][pt_t * 4 + p] = best[p];
    __syncthreads();

    if (tid < PTSB) {
        unsigned long long bk = red[0][tid];
        #pragma unroll
        for (int t = 1; t < 16; ++t) {
            unsigned long long v = red[t][tid];
            if (v < bk) bk = v;
        }
        int idx = (int)(unsigned int)bk;
        int n   = pt0 + tid;

        out[OFF_IDX + n] = (float)idx;
        atomicAdd(&d_count[idx], 1u);
        out[OFF_ENC + (unsigned long long)n * NE + (unsigned)idx] = 1.0f;

        // z_q gather + loss partial (straight-through: z_q_out == z_q in value)
        float errsum = 0.f;
        const float* er = emb + (size_t)idx * DIM;
        float* zq = out + OFF_ZQ + (size_t)b * BHW + hw0 + tid;
        #pragma unroll
        for (int c = 0; c < DIM; ++c) {
            float e  = __ldg(er + c);
            float zv = zs[c][tid];
            float df = e - zv;
            errsum   = fmaf(df, df, errsum);
            zq[(size_t)c * HW] = e;
        }
        // reduce over the 32 lanes of warp 0
        #pragma unroll
        for (int o = 16; o > 0; o >>= 1)
            errsum += __shfl_down_sync(0xFFFFFFFFu, errsum, o);
        if (tid == 0) atomicAdd(&d_loss, errsum);
    }
}

// ---------------------------------------------------------------- finalize scalars
__global__ void finalize_kernel(float* __restrict__ out) {
    __shared__ float warp_s[32];
    int t = threadIdx.x;  // 1024 threads
    float em = (float)d_count[t] * (1.0f / 32768.0f);
    float v  = em * logf(em + 1e-10f);
    #pragma unroll
    for (int o = 16; o > 0; o >>= 1) v += __shfl_down_sync(0xFFFFFFFFu, v, o);
    if ((t & 31) == 0) warp_s[t >> 5] = v;
    __syncthreads();
    if (t < 32) {
        float w = warp_s[t];
        #pragma unroll
        for (int o = 16; o > 0; o >>= 1) w += __shfl_down_sync(0xFFFFFFFFu, w, o);
        if (t == 0) {
            out[OFF_PERP] = expf(-w);
            out[OFF_LOSS] = 1.25f * d_loss * (1.0f / 2097152.0f);
        }
    }
}

// ---------------------------------------------------------------- launch
extern "C" void kernel_launch(void* const* d_in, const int* in_sizes, int n_in,
                              void* d_out, int out_size) {
    const float* z   = (const float*)d_in[0];
    const float* emb = (const float*)d_in[1];
    float*       out = (float*)d_out;

    prep_kernel<<<4, 256>>>(emb);
    vq_main_kernel<<<NPTS / PTSB, 128>>>(z, emb, out);
    finalize_kernel<<<1, 1024>>>(out);
}